// round 2
// baseline (speedup 1.0000x reference)
#include <cuda_runtime.h>

// Problem constants (fixed by the reference).
#define SEQ    2048
#define BATCH  4
#define HEADS  16
#define DKH    64
#define DMODEL 1024
#define NEGV   -100000000000.0f   // matches reference NEG
#define AP     68                 // smem pitch (floats) for 64-wide tiles
#define SQP    132                // smem pitch (floats) for 128-wide (q rows)
#define TQ     128                // query rows per attention CTA

// Scratch (device globals -- no allocations allowed anywhere).
//   g_q/g_k/g_v : (B, H, N, DKH)
//   g_ctx       : (B, N, H, DKH) == row-major (B*N, DMODEL)
__device__ float g_q[(size_t)BATCH * HEADS * SEQ * DKH];
__device__ float g_k[(size_t)BATCH * HEADS * SEQ * DKH];
__device__ float g_v[(size_t)BATCH * HEADS * SEQ * DKH];
__device__ float g_ctx[(size_t)BATCH * SEQ * DMODEL];

// ---------------------------------------------------------------------------
// SGEMM: C(8192 x 1024) = A(8192 x 1024) @ B(1024 x 1024) + bias
// 128x128 block tile, BK=8, 256 threads, 8x8 microtile, register prefetch.
// srcSel: 0 -> Ain param, 1 -> g_ctx
// dstSel: 0 -> Cout (row-major), 1/2/3 -> g_q/g_k/g_v in split-head layout
// ---------------------------------------------------------------------------
__global__ __launch_bounds__(256) void sgemm_kernel(
    const float* __restrict__ Ain, const float* __restrict__ Bw,
    const float* __restrict__ bias, float* __restrict__ Cout,
    int srcSel, int dstSel)
{
    __shared__ float As[8][132];   // stored transposed: As[k][m]
    __shared__ float Bs[8][132];   // Bs[k][n]

    const float* A = srcSel ? g_ctx : Ain;
    float* Cp = (dstSel == 0) ? Cout
              : (dstSel == 1) ? g_q
              : (dstSel == 2) ? g_k : g_v;

    const int tid  = threadIdx.x;
    const int trow = tid >> 4;          // 0..15
    const int tcol = tid & 15;          // 0..15
    const int m0   = blockIdx.y * 128;
    const int n0   = blockIdx.x * 128;

    const int arow = tid >> 1;          // 0..127
    const int ac4  = (tid & 1) * 4;     // 0 or 4
    const int brow = tid >> 5;          // 0..7
    const int bc4  = (tid & 31) * 4;    // 0..124

    const float* aptr = A  + (size_t)(m0 + arow) * DMODEL + ac4;
    const float* bptr = Bw + (size_t)brow * DMODEL + n0 + bc4;

    float acc[8][8];
#pragma unroll
    for (int i = 0; i < 8; i++)
#pragma unroll
        for (int j = 0; j < 8; j++) acc[i][j] = 0.f;

    // prefetch first k-slice
    float4 av = *(const float4*)aptr;
    float4 bv = *(const float4*)bptr;

    for (int k0 = 0; k0 < DMODEL; k0 += 8) {
        As[ac4 + 0][arow] = av.x;
        As[ac4 + 1][arow] = av.y;
        As[ac4 + 2][arow] = av.z;
        As[ac4 + 3][arow] = av.w;
        *(float4*)&Bs[brow][bc4] = bv;
        __syncthreads();

        if (k0 + 8 < DMODEL) {  // prefetch next slice during compute
            av = *(const float4*)(aptr + k0 + 8);
            bv = *(const float4*)(bptr + (size_t)(k0 + 8) * DMODEL);
        }

#pragma unroll
        for (int kk = 0; kk < 8; kk++) {
            float ar[8], br[8];
            *(float4*)(ar)     = *(const float4*)&As[kk][trow * 8];
            *(float4*)(ar + 4) = *(const float4*)&As[kk][trow * 8 + 4];
            *(float4*)(br)     = *(const float4*)&Bs[kk][tcol * 8];
            *(float4*)(br + 4) = *(const float4*)&Bs[kk][tcol * 8 + 4];
#pragma unroll
            for (int i = 0; i < 8; i++)
#pragma unroll
                for (int j = 0; j < 8; j++)
                    acc[i][j] = fmaf(ar[i], br[j], acc[i][j]);
        }
        __syncthreads();
    }

    const int gc = n0 + tcol * 8;
    float bj[8];
#pragma unroll
    for (int j = 0; j < 8; j++) bj[j] = bias[gc + j];

    if (dstSel == 0) {
#pragma unroll
        for (int i = 0; i < 8; i++) {
            const int gm = m0 + trow * 8 + i;
            float4 w0 = make_float4(acc[i][0] + bj[0], acc[i][1] + bj[1],
                                    acc[i][2] + bj[2], acc[i][3] + bj[3]);
            float4 w1 = make_float4(acc[i][4] + bj[4], acc[i][5] + bj[5],
                                    acc[i][6] + bj[6], acc[i][7] + bj[7]);
            *(float4*)(Cp + (size_t)gm * DMODEL + gc)     = w0;
            *(float4*)(Cp + (size_t)gm * DMODEL + gc + 4) = w1;
        }
    } else {
        // split-head: column gc -> (h, dk); 8-wide chunk stays in one head.
        const int h  = gc >> 6;
        const int dk = gc & 63;
#pragma unroll
        for (int i = 0; i < 8; i++) {
            const int gm = m0 + trow * 8 + i;
            const int bb = gm >> 11;       // / SEQ
            const int n  = gm & 2047;      // % SEQ
            const size_t idx = (((size_t)(bb * HEADS + h)) * SEQ + n) * DKH + dk;
            float4 w0 = make_float4(acc[i][0] + bj[0], acc[i][1] + bj[1],
                                    acc[i][2] + bj[2], acc[i][3] + bj[3]);
            float4 w1 = make_float4(acc[i][4] + bj[4], acc[i][5] + bj[5],
                                    acc[i][6] + bj[6], acc[i][7] + bj[7]);
            *(float4*)(Cp + idx)     = w0;
            *(float4*)(Cp + idx + 4) = w1;
        }
    }
}

// ---------------------------------------------------------------------------
// Flash-attention (fp32, online softmax), rank-1 outer-product mainloops.
// Grid: (SEQ/128, HEADS, BATCH). Block: 512 threads = 16(tx) x 32(ty).
// CTA: 128 query rows x full DKH, streaming 64-row K/V tiles.
// Thread (tx,ty) owns S/O rows 4*ty..+3, cols 4*tx..+3 (4x4 microtile).
// Q staged transposed (sqT[d][row]) so QK^T is a rank-1 update per d:
//   2 LDS.128 (one broadcast) feed 16 FFMA -> FMA-bound, not crossbar-bound.
// Dynamic smem: sqT[64][132] + skT[64][68] + sv[64][68] + sp[128][68]
//             = 103,424 B. Row reductions via width-16 butterfly shuffles.
// ---------------------------------------------------------------------------
__global__ __launch_bounds__(512) void attn_kernel(const int* __restrict__ mask)
{
    extern __shared__ float sh[];
    float* sqT = sh;                       // [DKH][SQP]  q transposed
    float* skT = sqT + DKH * SQP;          // [DKH][AP]   k transposed
    float* sv  = skT + DKH * AP;           // [64][AP]    v rows
    float* sp  = sv  + 64 * AP;            // [TQ][AP]    probabilities

    const int tid = threadIdx.x;
    const int tx  = tid & 15;
    const int ty  = tid >> 4;              // 0..31
    const int b   = blockIdx.z;
    const int h   = blockIdx.y;
    const int q0  = blockIdx.x * TQ;
    const size_t base = ((size_t)(b * HEADS + h)) * SEQ * DKH;

    // load q tile, store transposed: sqT[d][row] = q[row][d]
    for (int v4 = tid; v4 < TQ * 16; v4 += 512) {
        const int r = v4 >> 4, c = (v4 & 15) * 4;
        float4 qv = *(const float4*)(g_q + base + (size_t)(q0 + r) * DKH + c);
        sqT[(c + 0) * SQP + r] = qv.x;
        sqT[(c + 1) * SQP + r] = qv.y;
        sqT[(c + 2) * SQP + r] = qv.z;
        sqT[(c + 3) * SQP + r] = qv.w;
    }

    float m_i[4], l_i[4], o[4][4];
#pragma unroll
    for (int i = 0; i < 4; i++) {
        m_i[i] = -1e30f;
        l_i[i] = 0.f;
#pragma unroll
        for (int j = 0; j < 4; j++) o[i][j] = 0.f;
    }

    const float scale = 0.125f;  // 1/sqrt(64)

    for (int k0 = 0; k0 < SEQ; k0 += 64) {
        __syncthreads();   // prev PV done reading sv/sp before overwrite
        // stage K (transposed) and V tiles
        for (int v4 = tid; v4 < 64 * 16; v4 += 512) {
            const int r = v4 >> 4, c = (v4 & 15) * 4;
            float4 kv = *(const float4*)(g_k + base + (size_t)(k0 + r) * DKH + c);
            skT[(c + 0) * AP + r] = kv.x;
            skT[(c + 1) * AP + r] = kv.y;
            skT[(c + 2) * AP + r] = kv.z;
            skT[(c + 3) * AP + r] = kv.w;
            *(float4*)(sv + r * AP + c) =
                *(const float4*)(g_v + base + (size_t)(k0 + r) * DKH + c);
        }
        __syncthreads();

        // S = q @ k^T : rank-1 updates over d
        float s[4][4];
#pragma unroll
        for (int i = 0; i < 4; i++)
#pragma unroll
            for (int j = 0; j < 4; j++) s[i][j] = 0.f;

#pragma unroll 8
        for (int d = 0; d < DKH; d++) {
            const float4 a  = *(const float4*)(sqT + d * SQP + ty * 4);
            const float4 kr = *(const float4*)(skT + d * AP  + tx * 4);
            s[0][0] = fmaf(a.x, kr.x, s[0][0]);
            s[0][1] = fmaf(a.x, kr.y, s[0][1]);
            s[0][2] = fmaf(a.x, kr.z, s[0][2]);
            s[0][3] = fmaf(a.x, kr.w, s[0][3]);
            s[1][0] = fmaf(a.y, kr.x, s[1][0]);
            s[1][1] = fmaf(a.y, kr.y, s[1][1]);
            s[1][2] = fmaf(a.y, kr.z, s[1][2]);
            s[1][3] = fmaf(a.y, kr.w, s[1][3]);
            s[2][0] = fmaf(a.z, kr.x, s[2][0]);
            s[2][1] = fmaf(a.z, kr.y, s[2][1]);
            s[2][2] = fmaf(a.z, kr.z, s[2][2]);
            s[2][3] = fmaf(a.z, kr.w, s[2][3]);
            s[3][0] = fmaf(a.w, kr.x, s[3][0]);
            s[3][1] = fmaf(a.w, kr.y, s[3][1]);
            s[3][2] = fmaf(a.w, kr.z, s[3][2]);
            s[3][3] = fmaf(a.w, kr.w, s[3][3]);
        }

        // scale + mask ((B,1,N,N), shared over heads), vectorized int4
#pragma unroll
        for (int i = 0; i < 4; i++) {
            const int4 mv = *(const int4*)(mask
                + ((size_t)b * SEQ + (q0 + ty * 4 + i)) * SEQ + k0 + tx * 4);
            s[i][0] = (mv.x == 0) ? NEGV : s[i][0] * scale;
            s[i][1] = (mv.y == 0) ? NEGV : s[i][1] * scale;
            s[i][2] = (mv.z == 0) ? NEGV : s[i][2] * scale;
            s[i][3] = (mv.w == 0) ? NEGV : s[i][3] * scale;
        }

        // online softmax update (per row: butterfly over the 16 tx lanes)
#pragma unroll
        for (int i = 0; i < 4; i++) {
            float mx = fmaxf(fmaxf(s[i][0], s[i][1]), fmaxf(s[i][2], s[i][3]));
#pragma unroll
            for (int off = 1; off < 16; off <<= 1)
                mx = fmaxf(mx, __shfl_xor_sync(0xffffffffu, mx, off, 16));
            const float mnew  = fmaxf(m_i[i], mx);
            const float alpha = __expf(m_i[i] - mnew);
            m_i[i] = mnew;

            float rs = 0.f;
#pragma unroll
            for (int j = 0; j < 4; j++) {
                const float p = __expf(s[i][j] - mnew);
                s[i][j] = p;
                rs += p;
            }
#pragma unroll
            for (int off = 1; off < 16; off <<= 1)
                rs += __shfl_xor_sync(0xffffffffu, rs, off, 16);

            l_i[i] = l_i[i] * alpha + rs;
#pragma unroll
            for (int j = 0; j < 4; j++) o[i][j] *= alpha;
            *(float4*)(sp + (ty * 4 + i) * AP + tx * 4) =
                make_float4(s[i][0], s[i][1], s[i][2], s[i][3]);
        }
        __syncthreads();

        // O += P @ V : 4-wide j blocks, P rows read as broadcast float4
#pragma unroll 4
        for (int j0 = 0; j0 < 64; j0 += 4) {
            float4 pv[4], vr[4];
#pragma unroll
            for (int i = 0; i < 4; i++)
                pv[i] = *(const float4*)(sp + (ty * 4 + i) * AP + j0);
#pragma unroll
            for (int jj = 0; jj < 4; jj++)
                vr[jj] = *(const float4*)(sv + (j0 + jj) * AP + tx * 4);
#pragma unroll
            for (int i = 0; i < 4; i++) {
                o[i][0] = fmaf(pv[i].x, vr[0].x, o[i][0]);
                o[i][1] = fmaf(pv[i].x, vr[0].y, o[i][1]);
                o[i][2] = fmaf(pv[i].x, vr[0].z, o[i][2]);
                o[i][3] = fmaf(pv[i].x, vr[0].w, o[i][3]);
                o[i][0] = fmaf(pv[i].y, vr[1].x, o[i][0]);
                o[i][1] = fmaf(pv[i].y, vr[1].y, o[i][1]);
                o[i][2] = fmaf(pv[i].y, vr[1].z, o[i][2]);
                o[i][3] = fmaf(pv[i].y, vr[1].w, o[i][3]);
                o[i][0] = fmaf(pv[i].z, vr[2].x, o[i][0]);
                o[i][1] = fmaf(pv[i].z, vr[2].y, o[i][1]);
                o[i][2] = fmaf(pv[i].z, vr[2].z, o[i][2]);
                o[i][3] = fmaf(pv[i].z, vr[2].w, o[i][3]);
                o[i][0] = fmaf(pv[i].w, vr[3].x, o[i][0]);
                o[i][1] = fmaf(pv[i].w, vr[3].y, o[i][1]);
                o[i][2] = fmaf(pv[i].w, vr[3].z, o[i][2]);
                o[i][3] = fmaf(pv[i].w, vr[3].w, o[i][3]);
            }
        }
    }

    // normalize + write context in (B, N, H, DKH) layout
#pragma unroll
    for (int i = 0; i < 4; i++) {
        const float inv = 1.f / l_i[i];
        const int n = q0 + ty * 4 + i;
        float4 w = make_float4(o[i][0] * inv, o[i][1] * inv,
                               o[i][2] * inv, o[i][3] * inv);
        *(float4*)(g_ctx + (((size_t)(b * SEQ + n)) * HEADS + h) * DKH + tx * 4) = w;
    }
}

// ---------------------------------------------------------------------------
// Launcher. Inputs (metadata order): query, key, value, mask,
// Wq, bq, Wk, bk, Wv, bv, Wo, bo. Output: fp32 (B*N, DMODEL).
// Graph-capturable: kernel launches only (+ idempotent func-attr set).
// ---------------------------------------------------------------------------
extern "C" void kernel_launch(void* const* d_in, const int* in_sizes, int n_in,
                              void* d_out, int out_size)
{
    (void)in_sizes; (void)n_in; (void)out_size;
    const float* query = (const float*)d_in[0];
    const float* key_  = (const float*)d_in[1];
    const float* value = (const float*)d_in[2];
    const int*   mask  = (const int*)  d_in[3];
    const float* Wq = (const float*)d_in[4];
    const float* bq = (const float*)d_in[5];
    const float* Wk = (const float*)d_in[6];
    const float* bk = (const float*)d_in[7];
    const float* Wv = (const float*)d_in[8];
    const float* bv = (const float*)d_in[9];
    const float* Wo = (const float*)d_in[10];
    const float* bo = (const float*)d_in[11];
    float* out = (float*)d_out;

    const dim3 gg(DMODEL / 128, (BATCH * SEQ) / 128);

    // Q/K/V projections -> split-head scratch
    sgemm_kernel<<<gg, 256>>>(query, Wq, bq, nullptr, 0, 1);
    sgemm_kernel<<<gg, 256>>>(key_,  Wk, bk, nullptr, 0, 2);
    sgemm_kernel<<<gg, 256>>>(value, Wv, bv, nullptr, 0, 3);

    // Fused masked attention (flash-style)
    const int ATTN_SMEM = (DKH * SQP + DKH * AP + 64 * AP + TQ * AP)
                          * (int)sizeof(float);  // 103,424 B
    cudaFuncSetAttribute(attn_kernel,
                         cudaFuncAttributeMaxDynamicSharedMemorySize, ATTN_SMEM);
    attn_kernel<<<dim3(SEQ / TQ, HEADS, BATCH), 512, ATTN_SMEM>>>(mask);

    // Output projection -> d_out
    sgemm_kernel<<<gg, 256>>>(nullptr, Wo, bo, out, 1, 0);
}

// round 14
// speedup vs baseline: 1.3955x; 1.3955x over previous
#include <cuda_runtime.h>
#include <cuda_bf16.h>
#include <cstdint>

// Problem constants (fixed by the reference).
#define SEQ    2048
#define BATCH  4
#define HEADS  16
#define DKH    64
#define DMODEL 1024
#define MROWS  (BATCH * SEQ)          // 8192
#define NEGV   -100000000000.0f
#define AP     68
#define SQP    132
#define TQ     128

// ---------------------------------------------------------------------------
// Scratch device globals (no allocations allowed anywhere).
// ---------------------------------------------------------------------------
__device__ float g_q[(size_t)BATCH * HEADS * SEQ * DKH];
__device__ float g_k[(size_t)BATCH * HEADS * SEQ * DKH];
__device__ float g_v[(size_t)BATCH * HEADS * SEQ * DKH];
__device__ float g_ctx[(size_t)BATCH * SEQ * DMODEL];

// bf16 hi/lo split operands (reused across the 4 GEMMs).
// A: (8192 x 1024) K-major.  B: (1024n x 1024k) = W^T, K-major.
__device__ __align__(16) unsigned short g_ahi[(size_t)MROWS * DMODEL];
__device__ __align__(16) unsigned short g_alo[(size_t)MROWS * DMODEL];
__device__ __align__(16) unsigned short g_bhi[(size_t)DMODEL * DMODEL];
__device__ __align__(16) unsigned short g_blo[(size_t)DMODEL * DMODEL];

// ---------------------------------------------------------------------------
// Prep 1: elementwise hi/lo split of A (fp32 -> bf16 hi + bf16 lo residual).
// ---------------------------------------------------------------------------
__device__ __forceinline__ void split2(float v, unsigned short& h, unsigned short& l) {
    __nv_bfloat16 hb = __float2bfloat16_rn(v);
    float r = v - __bfloat162float(hb);
    __nv_bfloat16 lb = __float2bfloat16_rn(r);
    h = *reinterpret_cast<unsigned short*>(&hb);
    l = *reinterpret_cast<unsigned short*>(&lb);
}

__global__ __launch_bounds__(256) void split_kernel(const float* __restrict__ in, int srcSel)
{
    const float* src = srcSel ? g_ctx : in;
    size_t g = (size_t)blockIdx.x * 256 + threadIdx.x;   // 8-float group id
    float4 v0 = *(const float4*)(src + g * 8);
    float4 v1 = *(const float4*)(src + g * 8 + 4);
    unsigned short h[8], l[8];
    split2(v0.x, h[0], l[0]); split2(v0.y, h[1], l[1]);
    split2(v0.z, h[2], l[2]); split2(v0.w, h[3], l[3]);
    split2(v1.x, h[4], l[4]); split2(v1.y, h[5], l[5]);
    split2(v1.z, h[6], l[6]); split2(v1.w, h[7], l[7]);
    uint4 uh, ul;
    uh.x = h[0] | ((uint32_t)h[1] << 16); uh.y = h[2] | ((uint32_t)h[3] << 16);
    uh.z = h[4] | ((uint32_t)h[5] << 16); uh.w = h[6] | ((uint32_t)h[7] << 16);
    ul.x = l[0] | ((uint32_t)l[1] << 16); ul.y = l[2] | ((uint32_t)l[3] << 16);
    ul.z = l[4] | ((uint32_t)l[5] << 16); ul.w = l[6] | ((uint32_t)l[7] << 16);
    *(uint4*)(g_ahi + g * 8) = uh;
    *(uint4*)(g_alo + g * 8) = ul;
}

// ---------------------------------------------------------------------------
// Prep 2: W (1024k x 1024n) -> transposed hi/lo bf16 (n-major rows, K contig).
// ---------------------------------------------------------------------------
__global__ __launch_bounds__(256) void wsplit_kernel(const float* __restrict__ W)
{
    __shared__ float t[32][33];
    const int x = threadIdx.x, y0 = threadIdx.y;
    const int n0 = blockIdx.x * 32, k0 = blockIdx.y * 32;
#pragma unroll
    for (int i = 0; i < 4; i++)
        t[y0 + i * 8][x] = W[(size_t)(k0 + y0 + i * 8) * DMODEL + n0 + x];
    __syncthreads();
#pragma unroll
    for (int i = 0; i < 4; i++) {
        float v = t[x][y0 + i * 8];          // = W[k0+x][n0+y0+8i]
        unsigned short h, l;
        split2(v, h, l);
        size_t idx = (size_t)(n0 + y0 + i * 8) * DMODEL + k0 + x;
        g_bhi[idx] = h;
        g_blo[idx] = l;
    }
}

// ---------------------------------------------------------------------------
// mma.sync (baseline PTX, sm_80+ ISA -- assembles at compute_103, runs on the
// tensor pipe as HMMA). m16n8k16 row.col bf16 -> f32.
// ---------------------------------------------------------------------------
__device__ __forceinline__ void mma16816(float* c, const uint32_t* a, const uint32_t* b) {
    asm volatile(
        "mma.sync.aligned.m16n8k16.row.col.f32.bf16.bf16.f32 "
        "{%0,%1,%2,%3}, {%4,%5,%6,%7}, {%8,%9}, {%0,%1,%2,%3};"
        : "+f"(c[0]), "+f"(c[1]), "+f"(c[2]), "+f"(c[3])
        : "r"(a[0]), "r"(a[1]), "r"(a[2]), "r"(a[3]), "r"(b[0]), "r"(b[1]));
}

// ---------------------------------------------------------------------------
// HMMA GEMM: C(8192 x 1024) = A @ W + bias, bf16 hi/lo x3 passes, f32 accum.
// 128x128 block tile, 256 threads = 8 warps in 2(m) x 4(n); warp tile 64x32.
// K staged in 32-wide smem chunks (pitch 40 -> conflict-free fragment LDS).
// dstSel: 0 -> Cout row-major, 1/2/3 -> g_q/g_k/g_v split-head layout.
// ---------------------------------------------------------------------------
#define KP 40   // smem pitch in bf16 for 32-wide k chunks

__global__ __launch_bounds__(256, 2)
void hgemm_kernel(const float* __restrict__ bias, float* __restrict__ Cout, int dstSel)
{
    __shared__ __align__(16) unsigned short sA[2][128 * KP];  // [hi/lo][row][k]
    __shared__ __align__(16) unsigned short sB[2][128 * KP];  // [hi/lo][n][k]

    const int tid  = threadIdx.x;
    const int wid  = tid >> 5;
    const int lane = tid & 31;
    const int m0   = blockIdx.y * 128;
    const int n0   = blockIdx.x * 128;
    const int wm   = (wid >> 2) * 64;    // warp m offset within block
    const int wn   = (wid & 3) * 32;     // warp n offset within block
    const int r    = lane >> 2;          // fragment row group 0..7
    const int cp   = (lane & 3) * 2;     // fragment col pair 0,2,4,6

    float acc[4][4][4];                  // [m16 tile][n8 tile][c0..c3]
#pragma unroll
    for (int i = 0; i < 4; i++)
#pragma unroll
        for (int j = 0; j < 4; j++)
#pragma unroll
            for (int q = 0; q < 4; q++) acc[i][j][q] = 0.f;

    for (int k0 = 0; k0 < DMODEL; k0 += 32) {
        // stage 4 buffers: 512 uint4 chunks each, 2 per thread
#pragma unroll
        for (int c = tid; c < 512; c += 256) {
            const int row = c >> 2, cg = (c & 3) * 8;
            const size_t ga = (size_t)(m0 + row) * DMODEL + k0 + cg;
            const size_t gb = (size_t)(n0 + row) * DMODEL + k0 + cg;
            *(uint4*)&sA[0][row * KP + cg] = *(const uint4*)(g_ahi + ga);
            *(uint4*)&sA[1][row * KP + cg] = *(const uint4*)(g_alo + ga);
            *(uint4*)&sB[0][row * KP + cg] = *(const uint4*)(g_bhi + gb);
            *(uint4*)&sB[1][row * KP + cg] = *(const uint4*)(g_blo + gb);
        }
        __syncthreads();

#pragma unroll
        for (int kk = 0; kk < 32; kk += 16) {
            uint32_t ah[4][4], al[4][4], bf[4][2];
            // A fragments (hi + lo), 4 m16 tiles
#pragma unroll
            for (int i = 0; i < 4; i++) {
                const int ar = wm + i * 16 + r;
                ah[i][0] = *(const uint32_t*)&sA[0][ar * KP + kk + cp];
                ah[i][1] = *(const uint32_t*)&sA[0][(ar + 8) * KP + kk + cp];
                ah[i][2] = *(const uint32_t*)&sA[0][ar * KP + kk + cp + 8];
                ah[i][3] = *(const uint32_t*)&sA[0][(ar + 8) * KP + kk + cp + 8];
                al[i][0] = *(const uint32_t*)&sA[1][ar * KP + kk + cp];
                al[i][1] = *(const uint32_t*)&sA[1][(ar + 8) * KP + kk + cp];
                al[i][2] = *(const uint32_t*)&sA[1][ar * KP + kk + cp + 8];
                al[i][3] = *(const uint32_t*)&sA[1][(ar + 8) * KP + kk + cp + 8];
            }
            // B hi fragments, 4 n8 tiles
#pragma unroll
            for (int j = 0; j < 4; j++) {
                const int bn = wn + j * 8 + r;
                bf[j][0] = *(const uint32_t*)&sB[0][bn * KP + kk + cp];
                bf[j][1] = *(const uint32_t*)&sB[0][bn * KP + kk + cp + 8];
            }
            // pass 1: hi*hi ; pass 2: lo*hi
#pragma unroll
            for (int i = 0; i < 4; i++)
#pragma unroll
                for (int j = 0; j < 4; j++) {
                    mma16816(acc[i][j], ah[i], bf[j]);
                    mma16816(acc[i][j], al[i], bf[j]);
                }
            // B lo fragments (overwrite), pass 3: hi*lo
#pragma unroll
            for (int j = 0; j < 4; j++) {
                const int bn = wn + j * 8 + r;
                bf[j][0] = *(const uint32_t*)&sB[1][bn * KP + kk + cp];
                bf[j][1] = *(const uint32_t*)&sB[1][bn * KP + kk + cp + 8];
            }
#pragma unroll
            for (int i = 0; i < 4; i++)
#pragma unroll
                for (int j = 0; j < 4; j++)
                    mma16816(acc[i][j], ah[i], bf[j]);
        }
        __syncthreads();
    }

    // epilogue: c0,c1 at (row, gc..gc+1); c2,c3 at (row+8, gc..gc+1)
#pragma unroll
    for (int i = 0; i < 4; i++) {
#pragma unroll
        for (int j = 0; j < 4; j++) {
            const int row = m0 + wm + i * 16 + r;
            const int gc  = n0 + wn + j * 8 + cp;
            const float b0 = bias[gc], b1 = bias[gc + 1];
            float2 w0 = make_float2(acc[i][j][0] + b0, acc[i][j][1] + b1);
            float2 w1 = make_float2(acc[i][j][2] + b0, acc[i][j][3] + b1);
            if (dstSel == 0) {
                *(float2*)(Cout + (size_t)row * DMODEL + gc)       = w0;
                *(float2*)(Cout + (size_t)(row + 8) * DMODEL + gc) = w1;
            } else {
                float* Cp = (dstSel == 1) ? g_q : (dstSel == 2) ? g_k : g_v;
                const int h = gc >> 6, dk = gc & 63;   // gc even: pair in-head
                const int bb0 = row >> 11,       nn0 = row & 2047;
                const int bb1 = (row + 8) >> 11, nn1 = (row + 8) & 2047;
                *(float2*)(Cp + (((size_t)(bb0 * HEADS + h)) * SEQ + nn0) * DKH + dk) = w0;
                *(float2*)(Cp + (((size_t)(bb1 * HEADS + h)) * SEQ + nn1) * DKH + dk) = w1;
            }
        }
    }
}

// ---------------------------------------------------------------------------
// Flash-attention (fp32, online softmax).
// R2 ncu: occ=25% (1 CTA/SM) with issue=57%. __launch_bounds__(512, 2) caps
// regs at 64 -> 2 CTAs/SM (smem 2x103,424 = 202KB < 228KB), hiding
// barrier/shfl/exp latency bubbles. Math identical to the passing R2 version.
// ---------------------------------------------------------------------------
__global__ __launch_bounds__(512, 2) void attn_kernel(const int* __restrict__ mask)
{
    extern __shared__ float sh[];
    float* sqT = sh;
    float* skT = sqT + DKH * SQP;
    float* sv  = skT + DKH * AP;
    float* sp  = sv  + 64 * AP;

    const int tid = threadIdx.x;
    const int tx  = tid & 15;
    const int ty  = tid >> 4;
    const int b   = blockIdx.z;
    const int h   = blockIdx.y;
    const int q0  = blockIdx.x * TQ;
    const size_t base = ((size_t)(b * HEADS + h)) * SEQ * DKH;

    for (int v4 = tid; v4 < TQ * 16; v4 += 512) {
        const int rr = v4 >> 4, c = (v4 & 15) * 4;
        float4 qv = *(const float4*)(g_q + base + (size_t)(q0 + rr) * DKH + c);
        sqT[(c + 0) * SQP + rr] = qv.x;
        sqT[(c + 1) * SQP + rr] = qv.y;
        sqT[(c + 2) * SQP + rr] = qv.z;
        sqT[(c + 3) * SQP + rr] = qv.w;
    }

    float m_i[4], l_i[4], o[4][4];
#pragma unroll
    for (int i = 0; i < 4; i++) {
        m_i[i] = -1e30f; l_i[i] = 0.f;
#pragma unroll
        for (int j = 0; j < 4; j++) o[i][j] = 0.f;
    }
    const float scale = 0.125f;

    for (int k0 = 0; k0 < SEQ; k0 += 64) {
        __syncthreads();
        for (int v4 = tid; v4 < 64 * 16; v4 += 512) {
            const int rr = v4 >> 4, c = (v4 & 15) * 4;
            float4 kv = *(const float4*)(g_k + base + (size_t)(k0 + rr) * DKH + c);
            skT[(c + 0) * AP + rr] = kv.x;
            skT[(c + 1) * AP + rr] = kv.y;
            skT[(c + 2) * AP + rr] = kv.z;
            skT[(c + 3) * AP + rr] = kv.w;
            *(float4*)(sv + rr * AP + c) =
                *(const float4*)(g_v + base + (size_t)(k0 + rr) * DKH + c);
        }
        __syncthreads();

        float s[4][4];
#pragma unroll
        for (int i = 0; i < 4; i++)
#pragma unroll
            for (int j = 0; j < 4; j++) s[i][j] = 0.f;

#pragma unroll 8
        for (int d = 0; d < DKH; d++) {
            const float4 a  = *(const float4*)(sqT + d * SQP + ty * 4);
            const float4 kr = *(const float4*)(skT + d * AP  + tx * 4);
            s[0][0] = fmaf(a.x, kr.x, s[0][0]); s[0][1] = fmaf(a.x, kr.y, s[0][1]);
            s[0][2] = fmaf(a.x, kr.z, s[0][2]); s[0][3] = fmaf(a.x, kr.w, s[0][3]);
            s[1][0] = fmaf(a.y, kr.x, s[1][0]); s[1][1] = fmaf(a.y, kr.y, s[1][1]);
            s[1][2] = fmaf(a.y, kr.z, s[1][2]); s[1][3] = fmaf(a.y, kr.w, s[1][3]);
            s[2][0] = fmaf(a.z, kr.x, s[2][0]); s[2][1] = fmaf(a.z, kr.y, s[2][1]);
            s[2][2] = fmaf(a.z, kr.z, s[2][2]); s[2][3] = fmaf(a.z, kr.w, s[2][3]);
            s[3][0] = fmaf(a.w, kr.x, s[3][0]); s[3][1] = fmaf(a.w, kr.y, s[3][1]);
            s[3][2] = fmaf(a.w, kr.z, s[3][2]); s[3][3] = fmaf(a.w, kr.w, s[3][3]);
        }

#pragma unroll
        for (int i = 0; i < 4; i++) {
            const int4 mv = *(const int4*)(mask
                + ((size_t)b * SEQ + (q0 + ty * 4 + i)) * SEQ + k0 + tx * 4);
            s[i][0] = (mv.x == 0) ? NEGV : s[i][0] * scale;
            s[i][1] = (mv.y == 0) ? NEGV : s[i][1] * scale;
            s[i][2] = (mv.z == 0) ? NEGV : s[i][2] * scale;
            s[i][3] = (mv.w == 0) ? NEGV : s[i][3] * scale;
        }

#pragma unroll
        for (int i = 0; i < 4; i++) {
            float mx = fmaxf(fmaxf(s[i][0], s[i][1]), fmaxf(s[i][2], s[i][3]));
#pragma unroll
            for (int off = 1; off < 16; off <<= 1)
                mx = fmaxf(mx, __shfl_xor_sync(0xffffffffu, mx, off, 16));
            const float mnew  = fmaxf(m_i[i], mx);
            const float alpha = __expf(m_i[i] - mnew);
            m_i[i] = mnew;
            float rs = 0.f;
#pragma unroll
            for (int j = 0; j < 4; j++) {
                const float p = __expf(s[i][j] - mnew);
                s[i][j] = p; rs += p;
            }
#pragma unroll
            for (int off = 1; off < 16; off <<= 1)
                rs += __shfl_xor_sync(0xffffffffu, rs, off, 16);
            l_i[i] = l_i[i] * alpha + rs;
#pragma unroll
            for (int j = 0; j < 4; j++) o[i][j] *= alpha;
            *(float4*)(sp + (ty * 4 + i) * AP + tx * 4) =
                make_float4(s[i][0], s[i][1], s[i][2], s[i][3]);
        }
        __syncthreads();

#pragma unroll 4
        for (int j0 = 0; j0 < 64; j0 += 4) {
            float4 pv[4], vr[4];
#pragma unroll
            for (int i = 0; i < 4; i++)
                pv[i] = *(const float4*)(sp + (ty * 4 + i) * AP + j0);
#pragma unroll
            for (int jj = 0; jj < 4; jj++)
                vr[jj] = *(const float4*)(sv + (j0 + jj) * AP + tx * 4);
#pragma unroll
            for (int i = 0; i < 4; i++) {
                o[i][0] = fmaf(pv[i].x, vr[0].x, o[i][0]);
                o[i][1] = fmaf(pv[i].x, vr[0].y, o[i][1]);
                o[i][2] = fmaf(pv[i].x, vr[0].z, o[i][2]);
                o[i][3] = fmaf(pv[i].x, vr[0].w, o[i][3]);
                o[i][0] = fmaf(pv[i].y, vr[1].x, o[i][0]);
                o[i][1] = fmaf(pv[i].y, vr[1].y, o[i][1]);
                o[i][2] = fmaf(pv[i].y, vr[1].z, o[i][2]);
                o[i][3] = fmaf(pv[i].y, vr[1].w, o[i][3]);
                o[i][0] = fmaf(pv[i].z, vr[2].x, o[i][0]);
                o[i][1] = fmaf(pv[i].z, vr[2].y, o[i][1]);
                o[i][2] = fmaf(pv[i].z, vr[2].z, o[i][2]);
                o[i][3] = fmaf(pv[i].z, vr[2].w, o[i][3]);
                o[i][0] = fmaf(pv[i].w, vr[3].x, o[i][0]);
                o[i][1] = fmaf(pv[i].w, vr[3].y, o[i][1]);
                o[i][2] = fmaf(pv[i].w, vr[3].z, o[i][2]);
                o[i][3] = fmaf(pv[i].w, vr[3].w, o[i][3]);
            }
        }
    }

#pragma unroll
    for (int i = 0; i < 4; i++) {
        const float inv = 1.f / l_i[i];
        const int n = q0 + ty * 4 + i;
        float4 w = make_float4(o[i][0] * inv, o[i][1] * inv,
                               o[i][2] * inv, o[i][3] * inv);
        *(float4*)(g_ctx + (((size_t)(b * SEQ + n)) * HEADS + h) * DKH + tx * 4) = w;
    }
}

// ---------------------------------------------------------------------------
// Launcher. Inputs: query,key,value,mask,Wq,bq,Wk,bk,Wv,bv,Wo,bo. Out: fp32.
// Graph-capturable: kernel launches only (+ idempotent func-attr set).
// ---------------------------------------------------------------------------
extern "C" void kernel_launch(void* const* d_in, const int* in_sizes, int n_in,
                              void* d_out, int out_size)
{
    (void)in_sizes; (void)n_in; (void)out_size;
    const float* query = (const float*)d_in[0];
    const float* key_  = (const float*)d_in[1];
    const float* value = (const float*)d_in[2];
    const int*   mask  = (const int*)  d_in[3];
    const float* Wq = (const float*)d_in[4];
    const float* bq = (const float*)d_in[5];
    const float* Wk = (const float*)d_in[6];
    const float* bk = (const float*)d_in[7];
    const float* Wv = (const float*)d_in[8];
    const float* bv = (const float*)d_in[9];
    const float* Wo = (const float*)d_in[10];
    const float* bo = (const float*)d_in[11];
    float* out = (float*)d_out;

    const dim3 sg(4096), wg(32, 32), gg(DMODEL / 128, MROWS / 128);
    const dim3 wb(32, 8);

    // Q projection
    split_kernel<<<sg, 256>>>(query, 0);
    wsplit_kernel<<<wg, wb>>>(Wq);
    hgemm_kernel<<<gg, 256>>>(bq, nullptr, 1);
    // K projection
    split_kernel<<<sg, 256>>>(key_, 0);
    wsplit_kernel<<<wg, wb>>>(Wk);
    hgemm_kernel<<<gg, 256>>>(bk, nullptr, 2);
    // V projection
    split_kernel<<<sg, 256>>>(value, 0);
    wsplit_kernel<<<wg, wb>>>(Wv);
    hgemm_kernel<<<gg, 256>>>(bv, nullptr, 3);

    // Attention
    const int ATTN_SMEM = (DKH * SQP + DKH * AP + 64 * AP + TQ * AP)
                          * (int)sizeof(float);
    cudaFuncSetAttribute(attn_kernel,
                         cudaFuncAttributeMaxDynamicSharedMemorySize, ATTN_SMEM);
    attn_kernel<<<dim3(SEQ / TQ, HEADS, BATCH), 512, ATTN_SMEM>>>(mask);

    // Output projection
    split_kernel<<<sg, 256>>>(nullptr, 1);
    wsplit_kernel<<<wg, wb>>>(Wo);
    hgemm_kernel<<<gg, 256>>>(bo, out, 0);
}